// round 16
// baseline (speedup 1.0000x reference)
#include <cuda_runtime.h>

#define BB 2
#define CC 512
#define HH 256
#define WW 256
#define EPSV 1e-5f
#define NPC 444                              // persistent grid: 3 per SM, <= wave-1 capacity

#define CHUNK_ROWS 16
#define CHUNK_BYTES (CHUNK_ROWS * WW * 4)    // 16 KB
#define QROWS 64                             // rows per P1 unit (quarter plane)
#define NCHUNK (QROWS / CHUNK_ROWS)          // 4
#define NU1 (BB * CC * 4)                    // 4096 P1 units
#define T1TOT (NU1 + NPC)                    // tickets consumed per launch (exact)
#define NU4 (BB * CC * 8)                    // 8192 P4 units (32 KB each)
#define T4TOT (NU4 + NPC)

// ---------------- scratch (device globals; no allocations allowed) ----------
__device__ float g_y1p[4 * BB * CC * WW];    // [q][b*CC+c][w]  y1 partials
__device__ float g_y2[BB * CC * HH];         // [b][c][h]
__device__ float g_dot[CC * BB];             // flat [c][b] == num[b][k]
__device__ float g_h[BB * 2 * CC];           // [b][1024]
__device__ float g_logits[BB * CC];          // [b][c]

__device__ unsigned g_tick1;                 // P1 work-steal ticket (monotone)
__device__ unsigned g_tick4;                 // P4 work-steal ticket (monotone)
__device__ unsigned g_cnt[4];                // grid-barrier arrival counters
__device__ unsigned g_gen[4];                // grid-barrier generations (monotone)

__device__ __forceinline__ float4 ldcg4(const float4* p) { return __ldcg(p); }
__device__ __forceinline__ void prefetchL2(const void* p) {
    asm volatile("prefetch.global.L2 [%0];" :: "l"(p));
}
__device__ __forceinline__ float hsum4(float4 a) { return (a.x + a.y) + (a.z + a.w); }
__device__ __forceinline__ float dotp4(float4 a, float4 b) {
    return a.x * b.x + a.y * b.y + a.z * b.z + a.w * b.w;
}
__device__ __forceinline__ float4 relu4(float4 a, float r, float c) {
    float4 o;
    o.x = fmaxf(0.f, fmaf(a.x, r, c));
    o.y = fmaxf(0.f, fmaf(a.y, r, c));
    o.z = fmaxf(0.f, fmaf(a.z, r, c));
    o.w = fmaxf(0.f, fmaf(a.w, r, c));
    return o;
}
__device__ __forceinline__ void add4(float4& s, float4 a) {
    s.x += a.x; s.y += a.y; s.z += a.z; s.w += a.w;
}

// software grid barrier: all NPC CTAs co-resident.
__device__ __forceinline__ void gridbar(int i) {
    __syncthreads();
    if (threadIdx.x == 0) {
        __threadfence();
        volatile unsigned* genp = (volatile unsigned*)&g_gen[i];
        unsigned gen = *genp;                          // read BEFORE arriving
        unsigned arrived = atomicAdd(&g_cnt[i], 1u);
        if (arrived == NPC - 1) {
            atomicExch(&g_cnt[i], 0u);                 // reset for next replay
            __threadfence();
            atomicAdd(&g_gen[i], 1u);                  // release
        } else {
            while (*genp == gen) { __nanosleep(32); }
        }
        __threadfence();
    }
    __syncthreads();
}

// block-wide reductions over 256 threads (deterministic; all threads call)
__device__ __forceinline__ float blockMax256(float v, float* sh) {
    #pragma unroll
    for (int off = 16; off; off >>= 1) v = fmaxf(v, __shfl_xor_sync(0xffffffffu, v, off));
    int lane = threadIdx.x & 31, w = threadIdx.x >> 5;
    if (lane == 0) sh[w] = v;
    __syncthreads();
    if (threadIdx.x == 0) {
        float m = sh[0];
        #pragma unroll
        for (int i = 1; i < 8; ++i) m = fmaxf(m, sh[i]);
        sh[0] = m;
    }
    __syncthreads();
    float r = sh[0];
    __syncthreads();
    return r;
}
__device__ __forceinline__ float blockSum256(float v, float* sh) {
    #pragma unroll
    for (int off = 16; off; off >>= 1) v += __shfl_xor_sync(0xffffffffu, v, off);
    int lane = threadIdx.x & 31, w = threadIdx.x >> 5;
    if (lane == 0) sh[w] = v;
    __syncthreads();
    if (threadIdx.x == 0) {
        float s = sh[0];
        #pragma unroll
        for (int i = 1; i < 8; ++i) s += sh[i];
        sh[0] = s;
    }
    __syncthreads();
    float r = sh[0];
    __syncthreads();
    return r;
}

// ============================================================================
// kall: one persistent kernel, everything fused with work-stealing.
//   P1 : steal 4096 quarter-plane units; cp.async double-buffered dwconv.
//   A  : BN stats + ReLU + dot          (warp per channel)
//   B  : linear1                        (warp per output row)
//   C  : linear2                        (warp per output row)
//   D  : per-CTA redundant softmax      (no barrier, no scale round-trip)
//   P4 : steal 8192 copy-scale units.
// Tickets: each launch consumes exactly NUx+NPC ticks (one terminating tick
// per CTA), so ticket % (NUx+NPC) is replay-invariant under CUDA graphs.
// ============================================================================
__global__ __launch_bounds__(256, 4)
void kall(const float* __restrict__ x, float* __restrict__ out,
          const float* __restrict__ w1, const float* __restrict__ w2,
          const float* __restrict__ g1, const float* __restrict__ b1,
          const float* __restrict__ g2, const float* __restrict__ b2,
          const float* __restrict__ lw1, const float* __restrict__ lb1,
          const float* __restrict__ lw2, const float* __restrict__ lb2) {
    __shared__ float4 buf[2][CHUNK_BYTES / 16];   // 32 KB
    __shared__ float4 y1buf[8][64];               // 8 KB
    __shared__ float  w1s[QROWS];
    __shared__ float  sred[8];
    __shared__ int    s_next;

    int t    = threadIdx.x;
    int lane = t & 31;
    int wrp  = t >> 5;
    int h    = lane >> 4;
    int cg   = lane & 15;

    unsigned sbase0 = (unsigned)__cvta_generic_to_shared(&buf[0][0]);
    unsigned sbase1 = (unsigned)__cvta_generic_to_shared(&buf[1][0]);

    // ---------------- P1: steal quarter-plane dwconv units ------------------
    if (t == 0) s_next = (int)(atomicAdd(&g_tick1, 1u) % T1TOT);
    __syncthreads();
    int cur = s_next;

    while (cur < NU1) {
        int bc = cur >> 2;
        int qt = cur & 3;
        int c  = bc & (CC - 1);
        const char* gbase = (const char*)x + (size_t)bc * (HH * WW * 4)
                                           + (size_t)qt * (QROWS * WW * 4);

        if (t < QROWS) w1s[t] = w1[c * HH + qt * QROWS + t];
        float4 w2r0 = *(const float4*)(w2 + c * WW + (cg +  0) * 4);
        float4 w2r1 = *(const float4*)(w2 + c * WW + (cg + 16) * 4);
        float4 w2r2 = *(const float4*)(w2 + c * WW + (cg + 32) * 4);
        float4 w2r3 = *(const float4*)(w2 + c * WW + (cg + 48) * 4);

        // issue stage s into buf[s&1]
        #define ISSUE(s_) do {                                                     \
            unsigned sb = ((s_) & 1) ? sbase1 : sbase0;                            \
            const char* g = gbase + (size_t)(s_) * CHUNK_BYTES;                    \
            _Pragma("unroll")                                                      \
            for (int i_ = 0; i_ < 4; ++i_) {                                       \
                asm volatile("cp.async.cg.shared.global [%0], [%1], 16;"           \
                             :: "r"(sb + t * 16 + i_ * 4096),                      \
                                "l"(g + t * 16 + i_ * 4096) : "memory");           \
            }                                                                      \
            asm volatile("cp.async.commit_group;" ::: "memory");                   \
        } while (0)

        ISSUE(0);
        ISSUE(1);

        float4 acc0 = make_float4(0.f, 0.f, 0.f, 0.f);
        float4 acc1 = make_float4(0.f, 0.f, 0.f, 0.f);
        float4 acc2 = make_float4(0.f, 0.f, 0.f, 0.f);
        float4 acc3 = make_float4(0.f, 0.f, 0.f, 0.f);
        int row = 2 * wrp + h;

        #pragma unroll
        for (int s = 0; s < NCHUNK; ++s) {
            asm volatile("cp.async.wait_group 1;" ::: "memory");
            __syncthreads();
            if (s == 0 && t == 0)            // lookahead: hide ticket latency
                s_next = (int)(atomicAdd(&g_tick1, 1u) % T1TOT);

            const float4* rp = &buf[s & 1][row * 64];
            float4 v0 = rp[cg +  0];
            float4 v1 = rp[cg + 16];
            float4 v2 = rp[cg + 32];
            float4 v3 = rp[cg + 48];

            float wv = w1s[s * CHUNK_ROWS + row];
            acc0.x = fmaf(v0.x, wv, acc0.x); acc0.y = fmaf(v0.y, wv, acc0.y);
            acc0.z = fmaf(v0.z, wv, acc0.z); acc0.w = fmaf(v0.w, wv, acc0.w);
            acc1.x = fmaf(v1.x, wv, acc1.x); acc1.y = fmaf(v1.y, wv, acc1.y);
            acc1.z = fmaf(v1.z, wv, acc1.z); acc1.w = fmaf(v1.w, wv, acc1.w);
            acc2.x = fmaf(v2.x, wv, acc2.x); acc2.y = fmaf(v2.y, wv, acc2.y);
            acc2.z = fmaf(v2.z, wv, acc2.z); acc2.w = fmaf(v2.w, wv, acc2.w);
            acc3.x = fmaf(v3.x, wv, acc3.x); acc3.y = fmaf(v3.y, wv, acc3.y);
            acc3.z = fmaf(v3.z, wv, acc3.z); acc3.w = fmaf(v3.w, wv, acc3.w);

            float p = dotp4(v0, w2r0) + dotp4(v1, w2r1) + dotp4(v2, w2r2) + dotp4(v3, w2r3);
            p += __shfl_xor_sync(0xffffffffu, p, 8);
            p += __shfl_xor_sync(0xffffffffu, p, 4);
            p += __shfl_xor_sync(0xffffffffu, p, 2);
            p += __shfl_xor_sync(0xffffffffu, p, 1);
            if (cg == 0) g_y2[bc * HH + qt * QROWS + s * CHUNK_ROWS + row] = p;

            __syncthreads();
            if (s + 2 < NCHUNK) { ISSUE(s + 2); }
            else asm volatile("cp.async.commit_group;" ::: "memory");
        }
        #undef ISSUE

        // combine the two half-warps (rows 2w and 2w+1 share columns)
        acc0.x += __shfl_down_sync(0xffffffffu, acc0.x, 16);
        acc0.y += __shfl_down_sync(0xffffffffu, acc0.y, 16);
        acc0.z += __shfl_down_sync(0xffffffffu, acc0.z, 16);
        acc0.w += __shfl_down_sync(0xffffffffu, acc0.w, 16);
        acc1.x += __shfl_down_sync(0xffffffffu, acc1.x, 16);
        acc1.y += __shfl_down_sync(0xffffffffu, acc1.y, 16);
        acc1.z += __shfl_down_sync(0xffffffffu, acc1.z, 16);
        acc1.w += __shfl_down_sync(0xffffffffu, acc1.w, 16);
        acc2.x += __shfl_down_sync(0xffffffffu, acc2.x, 16);
        acc2.y += __shfl_down_sync(0xffffffffu, acc2.y, 16);
        acc2.z += __shfl_down_sync(0xffffffffu, acc2.z, 16);
        acc2.w += __shfl_down_sync(0xffffffffu, acc2.w, 16);
        acc3.x += __shfl_down_sync(0xffffffffu, acc3.x, 16);
        acc3.y += __shfl_down_sync(0xffffffffu, acc3.y, 16);
        acc3.z += __shfl_down_sync(0xffffffffu, acc3.z, 16);
        acc3.w += __shfl_down_sync(0xffffffffu, acc3.w, 16);

        if (h == 0) {
            y1buf[wrp][cg +  0] = acc0;
            y1buf[wrp][cg + 16] = acc1;
            y1buf[wrp][cg + 32] = acc2;
            y1buf[wrp][cg + 48] = acc3;
        }
        __syncthreads();

        if (t < 64) {
            float4 s = y1buf[0][t];
            #pragma unroll
            for (int i = 1; i < 8; ++i) add4(s, y1buf[i][t]);
            reinterpret_cast<float4*>(g_y1p + ((size_t)qt * BB * CC + bc) * WW)[t] = s;
        }
        __syncthreads();
        cur = s_next;
    }
    asm volatile("cp.async.wait_group 0;" ::: "memory");

    // ---- prefetch MLP weights into L2 (after this CTA's streaming is done) --
    {
        int gt = blockIdx.x * 256 + t;               // 0..113663 >= 32768
        if (gt < 16384)          prefetchL2((const char*)lw1 + (size_t)gt * 128);
        else if (gt < 32768)     prefetchL2((const char*)lw2 + (size_t)(gt - 16384) * 128);
    }

    gridbar(0);

    int gw = blockIdx.x * 8 + wrp;                   // global warp id, 0..3551

    // ---------------- A: BN stats + ReLU + dot (warp per channel) -----------
    if (gw < CC) {
        int c = gw;
        const size_t QS = (size_t)BB * CC * WW / 4;  // quarter stride (float4)
        const float4* y1b = reinterpret_cast<const float4*>(g_y1p);
        const float4* p20 = reinterpret_cast<const float4*>(g_y2 + c * HH);
        const float4* p21 = reinterpret_cast<const float4*>(g_y2 + CC * HH + c * HH);

        float4 a10a = make_float4(0.f, 0.f, 0.f, 0.f);
        float4 a10b = make_float4(0.f, 0.f, 0.f, 0.f);
        float4 a11a = make_float4(0.f, 0.f, 0.f, 0.f);
        float4 a11b = make_float4(0.f, 0.f, 0.f, 0.f);
        #pragma unroll
        for (int q = 0; q < 4; ++q) {
            add4(a10a, ldcg4(y1b + q * QS + (size_t)c * 64 + lane));
            add4(a10b, ldcg4(y1b + q * QS + (size_t)c * 64 + lane + 32));
            add4(a11a, ldcg4(y1b + q * QS + (size_t)(CC + c) * 64 + lane));
            add4(a11b, ldcg4(y1b + q * QS + (size_t)(CC + c) * 64 + lane + 32));
        }

        float4 a20a = ldcg4(p20 + lane), a20b = ldcg4(p20 + lane + 32);
        float4 a21a = ldcg4(p21 + lane), a21b = ldcg4(p21 + lane + 32);

        float s1 = hsum4(a10a) + hsum4(a10b) + hsum4(a11a) + hsum4(a11b);
        float q1 = dotp4(a10a, a10a) + dotp4(a10b, a10b) + dotp4(a11a, a11a) + dotp4(a11b, a11b);
        float s2 = hsum4(a20a) + hsum4(a20b) + hsum4(a21a) + hsum4(a21b);
        float q2 = dotp4(a20a, a20a) + dotp4(a20b, a20b) + dotp4(a21a, a21a) + dotp4(a21b, a21b);

        #pragma unroll
        for (int off = 16; off; off >>= 1) {
            s1 += __shfl_xor_sync(0xffffffffu, s1, off);
            q1 += __shfl_xor_sync(0xffffffffu, q1, off);
            s2 += __shfl_xor_sync(0xffffffffu, s2, off);
            q2 += __shfl_xor_sync(0xffffffffu, q2, off);
        }

        const float invn = 1.f / (float)(BB * WW);
        float m1 = s1 * invn, v1 = q1 * invn - m1 * m1;
        float m2 = s2 * invn, v2 = q2 * invn - m2 * m2;
        float r1 = rsqrtf(v1 + EPSV) * g1[c];
        float c1 = b1[c] - m1 * r1;
        float r2 = rsqrtf(v2 + EPSV) * g2[c];
        float c2 = b2[c] - m2 * r2;

        float d0 = dotp4(relu4(a10a, r1, c1), relu4(a20a, r2, c2))
                 + dotp4(relu4(a10b, r1, c1), relu4(a20b, r2, c2));
        float d1 = dotp4(relu4(a11a, r1, c1), relu4(a21a, r2, c2))
                 + dotp4(relu4(a11b, r1, c1), relu4(a21b, r2, c2));
        #pragma unroll
        for (int off = 16; off; off >>= 1) {
            d0 += __shfl_xor_sync(0xffffffffu, d0, off);
            d1 += __shfl_xor_sync(0xffffffffu, d1, off);
        }
        if (lane == 0) {
            g_dot[c * BB + 0] = d0;
            g_dot[c * BB + 1] = d1;
        }
    }

    gridbar(1);

    // ---------------- B: linear1, warp per output row (K=512) ---------------
    if (gw < 2 * CC) {
        int j = gw;
        const float4* wr = reinterpret_cast<const float4*>(lw1 + (size_t)j * CC);
        const float4* i0 = reinterpret_cast<const float4*>(g_dot);
        const float4* i1 = reinterpret_cast<const float4*>(g_dot + CC);
        float a0 = 0.f, a1 = 0.f;
        #pragma unroll
        for (int i = 0; i < 4; ++i) {
            float4 wq = __ldg(wr + lane + 32 * i);
            float4 v0 = ldcg4(i0 + lane + 32 * i);
            float4 v1 = ldcg4(i1 + lane + 32 * i);
            a0 += dotp4(wq, v0);
            a1 += dotp4(wq, v1);
        }
        #pragma unroll
        for (int off = 16; off; off >>= 1) {
            a0 += __shfl_xor_sync(0xffffffffu, a0, off);
            a1 += __shfl_xor_sync(0xffffffffu, a1, off);
        }
        if (lane == 0) {
            float bj = lb1[j];
            g_h[j]          = a0 + bj;
            g_h[2 * CC + j] = a1 + bj;
        }
    }

    gridbar(2);

    // ---------------- C: linear2, warp per output row (K=1024) --------------
    if (gw < CC) {
        int j = gw;
        const float4* wr = reinterpret_cast<const float4*>(lw2 + (size_t)j * 2 * CC);
        const float4* i0 = reinterpret_cast<const float4*>(g_h);
        const float4* i1 = reinterpret_cast<const float4*>(g_h + 2 * CC);
        float a0 = 0.f, a1 = 0.f;
        #pragma unroll
        for (int i = 0; i < 8; ++i) {
            float4 wq = __ldg(wr + lane + 32 * i);
            float4 v0 = ldcg4(i0 + lane + 32 * i);
            float4 v1 = ldcg4(i1 + lane + 32 * i);
            a0 += dotp4(wq, v0);
            a1 += dotp4(wq, v1);
        }
        #pragma unroll
        for (int off = 16; off; off >>= 1) {
            a0 += __shfl_xor_sync(0xffffffffu, a0, off);
            a1 += __shfl_xor_sync(0xffffffffu, a1, off);
        }
        if (lane == 0) {
            float bj = lb2[j];
            g_logits[j]      = a0 + bj;
            g_logits[CC + j] = a1 + bj;
        }
    }

    gridbar(3);

    // ---------------- D: per-CTA redundant softmax (deterministic) ----------
    float l0a = __ldcg(&g_logits[t]);
    float l0b = __ldcg(&g_logits[256 + t]);
    float l1a = __ldcg(&g_logits[CC + t]);
    float l1b = __ldcg(&g_logits[CC + 256 + t]);

    float M0 = blockMax256(fmaxf(l0a, l0b), sred);
    float S0 = blockSum256(expf(l0a - M0) + expf(l0b - M0), sred);
    float M1 = blockMax256(fmaxf(l1a, l1b), sred);
    float S1 = blockSum256(expf(l1a - M1) + expf(l1b - M1), sred);
    float inv0 = 1.f / S0, inv1 = 1.f / S1;

    // ---------------- P4: steal copy-scale units (32 KB each) ---------------
    if (t == 0) s_next = (int)(atomicAdd(&g_tick4, 1u) % T4TOT);
    __syncthreads();
    int c4 = s_next;

    while (c4 < NU4) {
        __syncthreads();                 // all threads captured c4
        if (t == 0) s_next = (int)(atomicAdd(&g_tick4, 1u) % T4TOT);  // lookahead

        int bc   = c4 >> 3;
        int part = c4 & 7;
        float lg = __ldcg(&g_logits[bc]);
        float s  = (bc < CC) ? (expf(lg - M0) * inv0) : (expf(lg - M1) * inv1);

        const float4* xp = reinterpret_cast<const float4*>(x)
                           + (size_t)bc * (HH * WW / 4) + part * 2048;
        float4*       op = reinterpret_cast<float4*>(out)
                           + (size_t)bc * (HH * WW / 4) + part * 2048;
        #pragma unroll
        for (int i = 0; i < 8; ++i) {
            float4 v = xp[i * 256 + t];
            v.x *= s; v.y *= s; v.z *= s; v.w *= s;
            __stcs(&op[i * 256 + t], v);
        }

        __syncthreads();
        c4 = s_next;
    }
}

// ============================================================================
extern "C" void kernel_launch(void* const* d_in, const int* in_sizes, int n_in,
                              void* d_out, int out_size) {
    const float* x   = (const float*)d_in[0];
    const float* w1  = (const float*)d_in[1];
    const float* w2  = (const float*)d_in[2];
    const float* g1  = (const float*)d_in[3];
    const float* b1  = (const float*)d_in[4];
    const float* g2  = (const float*)d_in[5];
    const float* b2  = (const float*)d_in[6];
    const float* lw1 = (const float*)d_in[7];
    const float* lb1 = (const float*)d_in[8];
    const float* lw2 = (const float*)d_in[9];
    const float* lb2 = (const float*)d_in[10];
    float* out = (float*)d_out;

    kall<<<NPC, 256>>>(x, out, w1, w2, g1, b1, g2, b2, lw1, lb1, lw2, lb2);
}

// round 17
// speedup vs baseline: 1.3290x; 1.3290x over previous
#include <cuda_runtime.h>

#define BB 2
#define CC 512
#define HH 256
#define WW 256
#define EPSV 1e-5f
#define NCTA 148            // persistent-kernel grid for kmid

#define CHUNK_ROWS 16
#define CHUNK_BYTES (CHUNK_ROWS * WW * 4)   // 16 KB
#define QROWS 64                            // rows per work unit (quarter plane)
#define NCHUNK (QROWS / CHUNK_ROWS)         // 4 chunks per unit
#define NUNIT (BB * CC * 4)                 // 4096 work units

// ---------------- scratch (device globals; no allocations allowed) ----------
__device__ float g_y1p[4 * BB * CC * WW];   // [q][b*CC+c][w]  y1 partials (4 MB)
__device__ float g_y2[BB * CC * HH];        // [b][c][h]
__device__ float g_dot[CC * BB];            // flat [c][b]; linear view == num[b][k]
__device__ float g_h[BB * 2 * CC];          // [b][1024]
__device__ float g_logits[BB * CC];         // [b][c]
__device__ float g_scale[BB * CC];          // [b][c]

__device__ unsigned g_cnt[3];               // grid-barrier arrival counters
__device__ unsigned g_gen[3];               // grid-barrier generations (monotone)

__device__ __forceinline__ float4 ldcg4(const float4* p) { return __ldcg(p); }
__device__ __forceinline__ void prefetchL2(const void* p) {
    asm volatile("prefetch.global.L2 [%0];" :: "l"(p));
}
__device__ __forceinline__ float hsum4(float4 a) { return (a.x + a.y) + (a.z + a.w); }
__device__ __forceinline__ float dotp4(float4 a, float4 b) {
    return a.x * b.x + a.y * b.y + a.z * b.z + a.w * b.w;
}
__device__ __forceinline__ float4 relu4(float4 a, float r, float c) {
    float4 o;
    o.x = fmaxf(0.f, fmaf(a.x, r, c));
    o.y = fmaxf(0.f, fmaf(a.y, r, c));
    o.z = fmaxf(0.f, fmaf(a.z, r, c));
    o.w = fmaxf(0.f, fmaf(a.w, r, c));
    return o;
}
__device__ __forceinline__ void add4(float4& s, float4 a) {
    s.x += a.x; s.y += a.y; s.z += a.z; s.w += a.w;
}

// ============================================================================
// k1: quarter-plane work units. cp.async double-buffered pipeline of 16KB
// chunks. y1 column sums -> per-quarter partials g_y1p[qt]; y2 rows disjoint.
// grid = 4096, block = 256. (Best-known k1: 44.1us @ 79% DRAM.)
// ============================================================================
__global__ __launch_bounds__(256) void k1(const float* __restrict__ x,
                                          const float* __restrict__ w1,
                                          const float* __restrict__ w2) {
    __shared__ float4 buf[2][CHUNK_BYTES / 16];   // 2 x 16KB
    __shared__ float4 y1buf[8][64];               // 8KB: per-warp y1 partials
    __shared__ float  w1s[QROWS];                 // 256B

    int unit = blockIdx.x;               // 0..4095
    int bc   = unit >> 2;                // plane index b*CC + c
    int qt   = unit & 3;                 // quarter index
    int c    = bc & (CC - 1);
    const char* gbase = (const char*)x + (size_t)bc * (HH * WW * 4) + (size_t)qt * (QROWS * WW * 4);

    int t    = threadIdx.x;
    int lane = t & 31;
    int w    = t >> 5;
    int h    = lane >> 4;                // half-warp (row select)
    int cg   = lane & 15;                // colgroup

    if (t < QROWS) w1s[t] = w1[c * HH + qt * QROWS + t];

    // per-thread w2 quads for float4 columns {cg, cg+16, cg+32, cg+48}
    float4 w2r0 = *(const float4*)(w2 + c * WW + (cg +  0) * 4);
    float4 w2r1 = *(const float4*)(w2 + c * WW + (cg + 16) * 4);
    float4 w2r2 = *(const float4*)(w2 + c * WW + (cg + 32) * 4);
    float4 w2r3 = *(const float4*)(w2 + c * WW + (cg + 48) * 4);

    unsigned sbase0 = (unsigned)__cvta_generic_to_shared(&buf[0][0]);
    unsigned sbase1 = (unsigned)__cvta_generic_to_shared(&buf[1][0]);

    auto issue = [&](int s) {
        unsigned sb = (s & 1) ? sbase1 : sbase0;
        const char* g = gbase + (size_t)s * CHUNK_BYTES;
        #pragma unroll
        for (int i = 0; i < 4; ++i) {
            asm volatile("cp.async.cg.shared.global [%0], [%1], 16;"
                         :: "r"(sb + t * 16 + i * 4096), "l"(g + t * 16 + i * 4096)
                         : "memory");
        }
        asm volatile("cp.async.commit_group;" ::: "memory");
    };

    issue(0);
    issue(1);

    float4 acc0 = make_float4(0.f, 0.f, 0.f, 0.f);
    float4 acc1 = make_float4(0.f, 0.f, 0.f, 0.f);
    float4 acc2 = make_float4(0.f, 0.f, 0.f, 0.f);
    float4 acc3 = make_float4(0.f, 0.f, 0.f, 0.f);

    int row = 2 * w + h;                 // row within chunk, 0..15

    #pragma unroll 1
    for (int s = 0; s < NCHUNK; ++s) {
        asm volatile("cp.async.wait_group 1;" ::: "memory");
        __syncthreads();

        const float4* rp = &buf[s & 1][row * 64];
        float4 v0 = rp[cg +  0];
        float4 v1 = rp[cg + 16];
        float4 v2 = rp[cg + 32];
        float4 v3 = rp[cg + 48];

        float wv = w1s[s * CHUNK_ROWS + row];
        acc0.x = fmaf(v0.x, wv, acc0.x); acc0.y = fmaf(v0.y, wv, acc0.y);
        acc0.z = fmaf(v0.z, wv, acc0.z); acc0.w = fmaf(v0.w, wv, acc0.w);
        acc1.x = fmaf(v1.x, wv, acc1.x); acc1.y = fmaf(v1.y, wv, acc1.y);
        acc1.z = fmaf(v1.z, wv, acc1.z); acc1.w = fmaf(v1.w, wv, acc1.w);
        acc2.x = fmaf(v2.x, wv, acc2.x); acc2.y = fmaf(v2.y, wv, acc2.y);
        acc2.z = fmaf(v2.z, wv, acc2.z); acc2.w = fmaf(v2.w, wv, acc2.w);
        acc3.x = fmaf(v3.x, wv, acc3.x); acc3.y = fmaf(v3.y, wv, acc3.y);
        acc3.z = fmaf(v3.z, wv, acc3.z); acc3.w = fmaf(v3.w, wv, acc3.w);

        float p = dotp4(v0, w2r0) + dotp4(v1, w2r1) + dotp4(v2, w2r2) + dotp4(v3, w2r3);
        p += __shfl_xor_sync(0xffffffffu, p, 8);
        p += __shfl_xor_sync(0xffffffffu, p, 4);
        p += __shfl_xor_sync(0xffffffffu, p, 2);
        p += __shfl_xor_sync(0xffffffffu, p, 1);
        if (cg == 0) g_y2[bc * HH + qt * QROWS + s * CHUNK_ROWS + row] = p;

        __syncthreads();                 // everyone done reading buf[s&1]
        if (s + 2 < NCHUNK) issue(s + 2);
        else asm volatile("cp.async.commit_group;" ::: "memory");  // keep count
    }

    // combine the two half-warps (rows 2w and 2w+1 share columns)
    acc0.x += __shfl_down_sync(0xffffffffu, acc0.x, 16);
    acc0.y += __shfl_down_sync(0xffffffffu, acc0.y, 16);
    acc0.z += __shfl_down_sync(0xffffffffu, acc0.z, 16);
    acc0.w += __shfl_down_sync(0xffffffffu, acc0.w, 16);
    acc1.x += __shfl_down_sync(0xffffffffu, acc1.x, 16);
    acc1.y += __shfl_down_sync(0xffffffffu, acc1.y, 16);
    acc1.z += __shfl_down_sync(0xffffffffu, acc1.z, 16);
    acc1.w += __shfl_down_sync(0xffffffffu, acc1.w, 16);
    acc2.x += __shfl_down_sync(0xffffffffu, acc2.x, 16);
    acc2.y += __shfl_down_sync(0xffffffffu, acc2.y, 16);
    acc2.z += __shfl_down_sync(0xffffffffu, acc2.z, 16);
    acc2.w += __shfl_down_sync(0xffffffffu, acc2.w, 16);
    acc3.x += __shfl_down_sync(0xffffffffu, acc3.x, 16);
    acc3.y += __shfl_down_sync(0xffffffffu, acc3.y, 16);
    acc3.z += __shfl_down_sync(0xffffffffu, acc3.z, 16);
    acc3.w += __shfl_down_sync(0xffffffffu, acc3.w, 16);

    if (h == 0) {
        y1buf[w][cg +  0] = acc0;
        y1buf[w][cg + 16] = acc1;
        y1buf[w][cg + 32] = acc2;
        y1buf[w][cg + 48] = acc3;
    }
    __syncthreads();

    if (t < 64) {
        float4 s = y1buf[0][t];
        #pragma unroll
        for (int i = 1; i < 8; ++i) add4(s, y1buf[i][t]);
        reinterpret_cast<float4*>(g_y1p + ((size_t)qt * BB * CC + bc) * WW)[t] = s;
    }
}

// ============================================================================
// software grid barrier: all NCTA CTAs co-resident (NCTA <= #SMs).
// ============================================================================
__device__ __forceinline__ void gridbar(int i) {
    __syncthreads();
    if (threadIdx.x == 0) {
        __threadfence();
        volatile unsigned* genp = (volatile unsigned*)&g_gen[i];
        unsigned gen = *genp;                          // read BEFORE arriving
        unsigned arrived = atomicAdd(&g_cnt[i], 1u);
        if (arrived == NCTA - 1) {
            atomicExch(&g_cnt[i], 0u);                 // reset for next replay
            __threadfence();
            atomicAdd(&g_gen[i], 1u);                  // release
        } else {
            while (*genp == gen) { __nanosleep(32); }
        }
        __threadfence();
    }
    __syncthreads();
}

// block-wide reductions over 256 threads (deterministic; all threads call)
__device__ __forceinline__ float blockMax256(float v, float* sh) {
    #pragma unroll
    for (int off = 16; off; off >>= 1) v = fmaxf(v, __shfl_xor_sync(0xffffffffu, v, off));
    int lane = threadIdx.x & 31, w = threadIdx.x >> 5;
    if (lane == 0) sh[w] = v;
    __syncthreads();
    if (threadIdx.x == 0) {
        float m = sh[0];
        #pragma unroll
        for (int i = 1; i < 8; ++i) m = fmaxf(m, sh[i]);
        sh[0] = m;
    }
    __syncthreads();
    float r = sh[0];
    __syncthreads();
    return r;
}
__device__ __forceinline__ float blockSum256(float v, float* sh) {
    #pragma unroll
    for (int off = 16; off; off >>= 1) v += __shfl_xor_sync(0xffffffffu, v, off);
    int lane = threadIdx.x & 31, w = threadIdx.x >> 5;
    if (lane == 0) sh[w] = v;
    __syncthreads();
    if (threadIdx.x == 0) {
        float s = sh[0];
        #pragma unroll
        for (int i = 1; i < 8; ++i) s += sh[i];
        sh[0] = s;
    }
    __syncthreads();
    float r = sh[0];
    __syncthreads();
    return r;
}

// ============================================================================
// kmid: fused BN+ReLU+dot -> linear1 -> linear2 -> softmax.
// Persistent, grid = NCTA, block = 256. MLP weights prefetched into L2.
// Phase D is now PARALLEL: every CTA computes the softmax stats redundantly
// (4KB of L2-hot logits) and writes a disjoint 7-element slice of g_scale —
// no serial CTA-0 tail.
// ============================================================================
__global__ __launch_bounds__(256) void kmid(const float* __restrict__ g1, const float* __restrict__ b1,
                                            const float* __restrict__ g2, const float* __restrict__ b2,
                                            const float* __restrict__ lw1, const float* __restrict__ lb1,
                                            const float* __restrict__ lw2, const float* __restrict__ lb2) {
    __shared__ float sred[8];
    int t    = threadIdx.x;
    int lane = t & 31;
    int wrp  = t >> 5;
    int gw   = blockIdx.x * 8 + wrp;

    // ---- prefetch MLP weights into L2 (1 line per thread) ----
    {
        int gt = blockIdx.x * 256 + t;
        if (gt < 16384)          prefetchL2((const char*)lw1 + (size_t)gt * 128);
        else if (gt < 32768)     prefetchL2((const char*)lw2 + (size_t)(gt - 16384) * 128);
    }

    // ---- phase A: per-channel BN stats + ReLU + dot (one warp per channel) --
    if (gw < CC) {
        int c = gw;
        const size_t QS = (size_t)BB * CC * WW / 4;   // quarter stride (float4)
        const float4* y1b = reinterpret_cast<const float4*>(g_y1p);
        const float4* p20 = reinterpret_cast<const float4*>(g_y2 + c * HH);
        const float4* p21 = reinterpret_cast<const float4*>(g_y2 + CC * HH + c * HH);

        float4 a10a = make_float4(0.f, 0.f, 0.f, 0.f);
        float4 a10b = make_float4(0.f, 0.f, 0.f, 0.f);
        float4 a11a = make_float4(0.f, 0.f, 0.f, 0.f);
        float4 a11b = make_float4(0.f, 0.f, 0.f, 0.f);
        #pragma unroll
        for (int q = 0; q < 4; ++q) {
            add4(a10a, ldcg4(y1b + q * QS + (size_t)c * 64 + lane));
            add4(a10b, ldcg4(y1b + q * QS + (size_t)c * 64 + lane + 32));
            add4(a11a, ldcg4(y1b + q * QS + (size_t)(CC + c) * 64 + lane));
            add4(a11b, ldcg4(y1b + q * QS + (size_t)(CC + c) * 64 + lane + 32));
        }

        float4 a20a = ldcg4(p20 + lane), a20b = ldcg4(p20 + lane + 32);
        float4 a21a = ldcg4(p21 + lane), a21b = ldcg4(p21 + lane + 32);

        float s1 = hsum4(a10a) + hsum4(a10b) + hsum4(a11a) + hsum4(a11b);
        float q1 = dotp4(a10a, a10a) + dotp4(a10b, a10b) + dotp4(a11a, a11a) + dotp4(a11b, a11b);
        float s2 = hsum4(a20a) + hsum4(a20b) + hsum4(a21a) + hsum4(a21b);
        float q2 = dotp4(a20a, a20a) + dotp4(a20b, a20b) + dotp4(a21a, a21a) + dotp4(a21b, a21b);

        #pragma unroll
        for (int off = 16; off; off >>= 1) {
            s1 += __shfl_xor_sync(0xffffffffu, s1, off);
            q1 += __shfl_xor_sync(0xffffffffu, q1, off);
            s2 += __shfl_xor_sync(0xffffffffu, s2, off);
            q2 += __shfl_xor_sync(0xffffffffu, q2, off);
        }

        const float invn = 1.f / (float)(BB * WW);
        float m1 = s1 * invn, v1 = q1 * invn - m1 * m1;
        float m2 = s2 * invn, v2 = q2 * invn - m2 * m2;
        float r1 = rsqrtf(v1 + EPSV) * g1[c];
        float c1 = b1[c] - m1 * r1;
        float r2 = rsqrtf(v2 + EPSV) * g2[c];
        float c2 = b2[c] - m2 * r2;

        float d0 = dotp4(relu4(a10a, r1, c1), relu4(a20a, r2, c2))
                 + dotp4(relu4(a10b, r1, c1), relu4(a20b, r2, c2));
        float d1 = dotp4(relu4(a11a, r1, c1), relu4(a21a, r2, c2))
                 + dotp4(relu4(a11b, r1, c1), relu4(a21b, r2, c2));
        #pragma unroll
        for (int off = 16; off; off >>= 1) {
            d0 += __shfl_xor_sync(0xffffffffu, d0, off);
            d1 += __shfl_xor_sync(0xffffffffu, d1, off);
        }
        if (lane == 0) {
            g_dot[c * BB + 0] = d0;
            g_dot[c * BB + 1] = d1;
        }
    }

    gridbar(0);

    // ---- phase B: layer1, one warp per output row j (K=512) ----
    if (gw < 2 * CC) {
        int j = gw;
        const float4* wr = reinterpret_cast<const float4*>(lw1 + (size_t)j * CC);
        const float4* i0 = reinterpret_cast<const float4*>(g_dot);
        const float4* i1 = reinterpret_cast<const float4*>(g_dot + CC);
        float a0 = 0.f, a1 = 0.f;
        #pragma unroll
        for (int i = 0; i < 4; ++i) {
            float4 wq = __ldg(wr + lane + 32 * i);
            float4 v0 = ldcg4(i0 + lane + 32 * i);
            float4 v1 = ldcg4(i1 + lane + 32 * i);
            a0 += dotp4(wq, v0);
            a1 += dotp4(wq, v1);
        }
        #pragma unroll
        for (int off = 16; off; off >>= 1) {
            a0 += __shfl_xor_sync(0xffffffffu, a0, off);
            a1 += __shfl_xor_sync(0xffffffffu, a1, off);
        }
        if (lane == 0) {
            float bj = lb1[j];
            g_h[j]          = a0 + bj;
            g_h[2 * CC + j] = a1 + bj;
        }
    }

    gridbar(1);

    // ---- phase C: layer2, one warp per output row j (K=1024) ----
    if (gw < CC) {
        int j = gw;
        const float4* wr = reinterpret_cast<const float4*>(lw2 + (size_t)j * 2 * CC);
        const float4* i0 = reinterpret_cast<const float4*>(g_h);
        const float4* i1 = reinterpret_cast<const float4*>(g_h + 2 * CC);
        float a0 = 0.f, a1 = 0.f;
        #pragma unroll
        for (int i = 0; i < 8; ++i) {
            float4 wq = __ldg(wr + lane + 32 * i);
            float4 v0 = ldcg4(i0 + lane + 32 * i);
            float4 v1 = ldcg4(i1 + lane + 32 * i);
            a0 += dotp4(wq, v0);
            a1 += dotp4(wq, v1);
        }
        #pragma unroll
        for (int off = 16; off; off >>= 1) {
            a0 += __shfl_xor_sync(0xffffffffu, a0, off);
            a1 += __shfl_xor_sync(0xffffffffu, a1, off);
        }
        if (lane == 0) {
            float bj = lb2[j];
            g_logits[j]      = a0 + bj;
            g_logits[CC + j] = a1 + bj;
        }
    }

    gridbar(2);

    // ---- phase D: PARALLEL softmax — all CTAs redundantly compute stats, ----
    // ---- each writes a disjoint 7-element slice of g_scale.             ----
    {
        float l0a = __ldcg(&g_logits[t]);
        float l0b = __ldcg(&g_logits[256 + t]);
        float l1a = __ldcg(&g_logits[CC + t]);
        float l1b = __ldcg(&g_logits[CC + 256 + t]);

        float M0 = blockMax256(fmaxf(l0a, l0b), sred);
        float S0 = blockSum256(expf(l0a - M0) + expf(l0b - M0), sred);
        float M1 = blockMax256(fmaxf(l1a, l1b), sred);
        float S1 = blockSum256(expf(l1a - M1) + expf(l1b - M1), sred);
        float inv0 = 1.f / S0, inv1 = 1.f / S1;

        int base = blockIdx.x * 7;                    // 148*7 = 1036 >= 1024
        if (t < 7) {
            int f = base + t;
            if (f < BB * CC) {
                float lg = __ldcg(&g_logits[f]);
                g_scale[f] = (f < CC) ? (expf(lg - M0) * inv0)
                                      : (expf(lg - M1) * inv1);
            }
        }
    }
}

// ============================================================================
// k4: out = x * scale[b,c]. Reversed plane order + streaming stores (the exact
// configuration of the best run).
// ============================================================================
__global__ __launch_bounds__(256) void k4(const float* __restrict__ x, float* __restrict__ out) {
    int idx  = (BB * CC * 8 - 1) - blockIdx.x;   // reversed schedule
    int bc   = idx >> 3;
    int part = idx & 7;
    float s = __ldcg(&g_scale[bc]);

    const float4* xp = reinterpret_cast<const float4*>(x)   + (size_t)bc * (HH * WW / 4) + part * 2048;
    float4*       op = reinterpret_cast<float4*>(out)       + (size_t)bc * (HH * WW / 4) + part * 2048;

    int t = threadIdx.x;
    #pragma unroll
    for (int i = 0; i < 8; ++i) {
        float4 v = xp[i * 256 + t];
        v.x *= s; v.y *= s; v.z *= s; v.w *= s;
        __stcs(&op[i * 256 + t], v);
    }
}

// ============================================================================
extern "C" void kernel_launch(void* const* d_in, const int* in_sizes, int n_in,
                              void* d_out, int out_size) {
    const float* x   = (const float*)d_in[0];
    const float* w1  = (const float*)d_in[1];
    const float* w2  = (const float*)d_in[2];
    const float* g1  = (const float*)d_in[3];
    const float* b1  = (const float*)d_in[4];
    const float* g2  = (const float*)d_in[5];
    const float* b2  = (const float*)d_in[6];
    const float* lw1 = (const float*)d_in[7];
    const float* lb1 = (const float*)d_in[8];
    const float* lw2 = (const float*)d_in[9];
    const float* lb2 = (const float*)d_in[10];
    float* out = (float*)d_out;

    k1<<<NUNIT, 256>>>(x, w1, w2);
    kmid<<<NCTA, 256>>>(g1, b1, g2, b2, lw1, lb1, lw2, lb2);
    k4<<<BB * CC * 8, 256>>>(x, out);
}